// round 14
// baseline (speedup 1.0000x reference)
#include <cuda_runtime.h>
#include <cstdint>

// Problem dims (fixed: T=2048, B=32, D=512)
#define T_DIM 2048
#define B_DIM 32
#define D_DIM 512
#define M_DIM (T_DIM * B_DIM)   // 65536 GEMM rows
#define BD    (B_DIM * D_DIM)   // 16384 scan lanes

// Scratch: Y = x @ W^T + b (fp32, 134 MB)
__device__ float g_Y[(size_t)M_DIM * D_DIM];

// ---------------------------------------------------------------------------
// SGEMM: Y[m,e] = sum_k X[m,k]*W[e,k] + bias[e]
// CONSTRAINT: per output, fp32 fmaf chain with k strictly ascending 0..511
// (bit-matches the reference rounding; any reassociation flips spikes).
// Round-12 structure exactly (CTA 128x128, 8 warps 4mx2n, tile 8mx8n n-pairs,
// BKT=16 double buffer, occ 2, n-inner grid). ONE change: A stored DUPLICATED
// ({v,v} float2) in a swizzled smem array; per k the 8 packed f32x2 A operands
// come from 4 conflict-free LDS.128 -> zero pack MOVs. 38 issues/warp-k vs 45.
// Swizzle a^=((a>>6)&3)<<4 spreads the 4 lm-groups' 64B-spaced reads across
// banks {0-3},{20-23},{8-11},{28-31}: 1 wavefront per LDS.128.
// ---------------------------------------------------------------------------
#define BMT 128
#define BNT 128
#define BKT 16
#define NKT (D_DIM / BKT)   // 32

typedef unsigned long long u64t;

// 16B-granule XOR swizzle on byte offsets (rows are 1024B => k/buf invariant)
#define ASW(a) ((a) ^ ((((a) >> 6) & 3u) << 4))

__device__ __forceinline__ void ffma2(u64t& d, u64t a, u64t b) {
    asm("fma.rn.f32x2 %0, %1, %2, %0;" : "+l"(d) : "l"(a), "l"(b));
}
__device__ __forceinline__ void unpack2(u64t p, float& lo, float& hi) {
    asm("mov.b64 {%0, %1}, %2;" : "=f"(lo), "=f"(hi) : "l"(p));
}

__global__ __launch_bounds__(256, 2)
void sgemm_kernel(const float* __restrict__ X, const float* __restrict__ Wm,
                  const float* __restrict__ bias) {
    // A duplicated: [2][BKT][2*BMT] floats = 32 KB; B: [2][BKT][BNT] = 16 KB
    __shared__ __align__(1024) float Ad[2 * BKT * 2 * BMT];
    __shared__ __align__(16)   float Bs[2][BKT][BNT];
    char* Abase = (char*)Ad;

    const int tid = threadIdx.x;
    const int bn  = blockIdx.x * BNT;   // 4 values, inner -> X L2 reuse
    const int bm  = blockIdx.y * BMT;   // 512 values

    // 8 warps = 4(m) x 2(n); warp tile 32m x 64n; thread tile 8m x 8n
    const int wid    = tid >> 5;
    const int lane   = tid & 31;
    const int warp_m = wid >> 1;              // 0..3
    const int warp_n = wid & 1;               // 0..1
    const int lm     = lane >> 3;             // 0..3
    const int ln     = lane & 7;              // 0..7
    const int tm0    = warp_m * 32 + lm * 8;  // 8 consecutive m rows
    const int bn0    = warp_n * 64 + ln * 4;  // + q*32, q=0..1 (4 cols each)

    // gmem load mapping: 4 threads per row (one float4 of k each), 2 sweeps
    const int gr = tid >> 2;                  // 0..63
    const int gk = (tid & 3) << 2;            // 0,4,8,12

    const float* Xg = X  + (size_t)(bm + gr) * D_DIM + gk;
    const float* Wg = Wm + (size_t)(bn + gr) * D_DIM + gk;

    // acc[i][j]: rows i=0..7; j = q*2+h -> cols bn0 + q*32 + h*2 + {0,1}
    u64t acc[8][4];
#pragma unroll
    for (int i = 0; i < 8; i++)
#pragma unroll
        for (int j = 0; j < 4; j++) acc[i][j] = 0ull;

    // A dup store helper offsets: row (buf*BKT + kk) is 1024B
#define A_ST(bufkk, m, v)                                                    \
    *(float2*)(Abase + ASW((uint32_t)((bufkk) * 1024 + 8 * (m)))) =          \
        make_float2((v), (v))

    // prologue: chunk 0 -> buffer 0
    {
        float4 a0 = *(const float4*)(Xg);
        float4 a1 = *(const float4*)(Xg + (size_t)64 * D_DIM);
        float4 b0 = *(const float4*)(Wg);
        float4 b1 = *(const float4*)(Wg + (size_t)64 * D_DIM);
#pragma unroll
        for (int c = 0; c < 4; c++) {
            A_ST(gk + c, gr,      ((const float*)&a0)[c]);
            A_ST(gk + c, gr + 64, ((const float*)&a1)[c]);
            Bs[0][gk + c][gr]      = ((const float*)&b0)[c];
            Bs[0][gk + c][gr + 64] = ((const float*)&b1)[c];
        }
    }
    __syncthreads();

    for (int kt = 1; kt <= NKT; kt++) {
        const int buf = (kt - 1) & 1;

        float4 na0, na1, nb0, nb1;
        if (kt < NKT) {
            const int k0 = kt * BKT;
            na0 = *(const float4*)(Xg + k0);
            na1 = *(const float4*)(Xg + k0 + (size_t)64 * D_DIM);
            nb0 = *(const float4*)(Wg + k0);
            nb1 = *(const float4*)(Wg + k0 + (size_t)64 * D_DIM);
        }

#pragma unroll
        for (int k = 0; k < BKT; k++) {
            const uint32_t kb = (uint32_t)((buf * BKT + k) * 1024 + 8 * tm0);
            // A: 4 conflict-free LDS.128 -> 8 pre-packed {v,v} f32x2 operands
            u64t ad[8];
#pragma unroll
            for (int j = 0; j < 4; j++) {
                ulonglong2 a2 = *(const ulonglong2*)(Abase + ASW(kb + 16 * j));
                ad[2 * j + 0] = a2.x;
                ad[2 * j + 1] = a2.y;
            }

            u64t bp[4];
#pragma unroll
            for (int q = 0; q < 2; q++) {
                // 8 lanes (ln) cover one contiguous 128B block: conflict-free
                ulonglong2 b2 = *(const ulonglong2*)&Bs[buf][k][bn0 + q * 32];
                bp[q * 2 + 0] = b2.x;
                bp[q * 2 + 1] = b2.y;
            }

#pragma unroll
            for (int i = 0; i < 8; i++)
#pragma unroll
                for (int j = 0; j < 4; j++)
                    ffma2(acc[i][j], ad[i], bp[j]);
        }

        if (kt < NKT) {
            const int nbuf = kt & 1;
#pragma unroll
            for (int c = 0; c < 4; c++) {
                A_ST(nbuf * BKT + gk + c, gr,      ((const float*)&na0)[c]);
                A_ST(nbuf * BKT + gk + c, gr + 64, ((const float*)&na1)[c]);
                Bs[nbuf][gk + c][gr]      = ((const float*)&nb0)[c];
                Bs[nbuf][gk + c][gr + 64] = ((const float*)&nb1)[c];
            }
        }
        __syncthreads();
    }

    // epilogue: + bias (scalar fp32 adds, bit-identical), store Y
#pragma unroll
    for (int q = 0; q < 2; q++) {
        const int col = bn + bn0 + q * 32;
        const float4 bi = *(const float4*)(bias + col);
#pragma unroll
        for (int i = 0; i < 8; i++) {
            float v0, v1, v2, v3;
            unpack2(acc[i][q * 2 + 0], v0, v1);
            unpack2(acc[i][q * 2 + 1], v2, v3);
            float4 o = {v0 + bi.x, v1 + bi.y, v2 + bi.z, v3 + bi.w};
            *(float4*)(g_Y + (size_t)(bm + tm0 + i) * D_DIM + col) = o;
        }
    }
#undef A_ST
}

// ---------------------------------------------------------------------------
// Fused fwd+bwd LIF scan, time-chunked with warm-up (verified exact).
// ---------------------------------------------------------------------------
#define L_CH  256
#define W_UP  96
#define NCH   (T_DIM / L_CH)
#define UNR   16

__device__ __forceinline__ void lif_step(float& v, float c, bool& s) {
    v = v + (c - v) * 0.5f;
    s = (v >= 1.0f);
    v = s ? 0.0f : v;
}

__global__ void scan_kernel(float* __restrict__ out) {
    const int l  = blockIdx.x * blockDim.x + threadIdx.x;
    const int t0 = blockIdx.y * L_CH;
    unsigned fb[L_CH / 32];

    float v = 0.0f;
    {
        const int tb = (t0 - W_UP < 0) ? 0 : (t0 - W_UP);
        for (int tw = tb; tw < t0; tw += UNR) {
            float c[UNR];
#pragma unroll
            for (int i = 0; i < UNR; i++) c[i] = g_Y[(size_t)(tw + i) * BD + l];
#pragma unroll
            for (int i = 0; i < UNR; i++) { bool s; lif_step(v, c[i], s); }
        }
#pragma unroll
        for (int w = 0; w < L_CH / 32; w++) {
            unsigned bits = 0;
#pragma unroll 1
            for (int h = 0; h < 2; h++) {
                float c[UNR];
#pragma unroll
                for (int i = 0; i < UNR; i++)
                    c[i] = g_Y[(size_t)(t0 + w * 32 + h * UNR + i) * BD + l];
#pragma unroll
                for (int i = 0; i < UNR; i++) {
                    bool s; lif_step(v, c[i], s);
                    bits |= (unsigned)s << (h * UNR + i);
                }
            }
            fb[w] = bits;
        }
    }

    v = 0.0f;
    {
        const int te = (t0 + L_CH + W_UP > T_DIM) ? T_DIM : (t0 + L_CH + W_UP);
        for (int tw = te; tw > t0 + L_CH; tw -= UNR) {
            float c[UNR];
#pragma unroll
            for (int i = 0; i < UNR; i++) c[i] = g_Y[(size_t)(tw - 1 - i) * BD + l];
#pragma unroll
            for (int i = 0; i < UNR; i++) { bool s; lif_step(v, c[i], s); }
        }
#pragma unroll
        for (int w = L_CH / 32 - 1; w >= 0; w--) {
            const unsigned bits = fb[w];
#pragma unroll 1
            for (int h = 1; h >= 0; h--) {
                float c[UNR];
#pragma unroll
                for (int i = 0; i < UNR; i++)
                    c[i] = g_Y[(size_t)(t0 + w * 32 + h * UNR + (UNR - 1) - i) * BD + l];
#pragma unroll
                for (int i = 0; i < UNR; i++) {
                    const int ti = h * UNR + (UNR - 1) - i;
                    bool s; lif_step(v, c[i], s);
                    out[(size_t)(t0 + w * 32 + ti) * BD + l] =
                        (s ? 1.0f : 0.0f) + (float)((bits >> ti) & 1u);
                }
            }
        }
    }
}

// ---------------------------------------------------------------------------
extern "C" void kernel_launch(void* const* d_in, const int* in_sizes, int n_in,
                              void* d_out, int out_size) {
    const float* x = (const float*)d_in[0];
    const float* W = (const float*)d_in[1];
    const float* b = (const float*)d_in[2];
    float* out = (float*)d_out;

    dim3 ggrid(D_DIM / BNT, M_DIM / BMT);   // (4, 512): n inner -> X L2 reuse
    sgemm_kernel<<<ggrid, 256>>>(x, W, b);

    dim3 sgrid(BD / 256, NCH);              // (64, 8)
    scan_kernel<<<sgrid, 256>>>(out);
}

// round 15
// speedup vs baseline: 1.4779x; 1.4779x over previous
#include <cuda_runtime.h>
#include <cstdint>

// Problem dims (fixed: T=2048, B=32, D=512)
#define T_DIM 2048
#define B_DIM 32
#define D_DIM 512
#define M_DIM (T_DIM * B_DIM)   // 65536 GEMM rows
#define BD    (B_DIM * D_DIM)   // 16384 scan lanes

// Scratch: Y = x @ W^T + b (fp32, 134 MB)
__device__ float g_Y[(size_t)M_DIM * D_DIM];

// ---------------------------------------------------------------------------
// SGEMM: Y[m,e] = sum_k X[m,k]*W[e,k] + bias[e]
// CONSTRAINT: per output, fp32 fmaf chain with k strictly ascending 0..511
// (bit-matches the reference rounding; any reassociation flips spikes).
// FROZEN round-12 core (best measured: ~593us GEMM): CTA 128x128, 8 warps
// 4mx2n, thread tile 8mx8n with fma.rn.f32x2 n-pairs, BKT=16 double buffer,
// occ 2 (2 CTAs/SM), n-inner grid for X L2 reuse. Pipe-bound at ~85-95% of
// the FFMA2 rt=2 ceiling; pack-MOV-removal variants all regressed (r9/10/13/14).
// ---------------------------------------------------------------------------
#define BMT 128
#define BNT 128
#define BKT 16
#define NKT (D_DIM / BKT)   // 32

typedef unsigned long long u64t;

__device__ __forceinline__ void ffma2(u64t& d, u64t a, u64t b) {
    asm("fma.rn.f32x2 %0, %1, %2, %0;" : "+l"(d) : "l"(a), "l"(b));
}
__device__ __forceinline__ u64t pack_dup(float x) {
    u64t r;
    asm("mov.b64 %0, {%1, %1};" : "=l"(r) : "f"(x));
    return r;
}
__device__ __forceinline__ void unpack2(u64t p, float& lo, float& hi) {
    asm("mov.b64 {%0, %1}, %2;" : "=f"(lo), "=f"(hi) : "l"(p));
}

__global__ __launch_bounds__(256, 2)
void sgemm_kernel(const float* __restrict__ X, const float* __restrict__ Wm,
                  const float* __restrict__ bias) {
    __shared__ __align__(16) float As[2][BKT][BMT];   // 16 KB
    __shared__ __align__(16) float Bs[2][BKT][BNT];   // 16 KB

    const int tid = threadIdx.x;
    const int bn  = blockIdx.x * BNT;   // 4 values, inner -> X L2 reuse
    const int bm  = blockIdx.y * BMT;   // 512 values

    // 8 warps = 4(m) x 2(n); warp tile 32m x 64n; thread tile 8m x 8n
    const int wid    = tid >> 5;
    const int lane   = tid & 31;
    const int warp_m = wid >> 1;              // 0..3
    const int warp_n = wid & 1;               // 0..1
    const int lm     = lane >> 3;             // 0..3
    const int ln     = lane & 7;              // 0..7
    const int tm0    = warp_m * 32 + lm * 8;  // 8 consecutive m rows
    const int bn0    = warp_n * 64 + ln * 4;  // + q*32, q=0..1 (4 cols each)

    // gmem load mapping: 4 threads per row (one float4 of k each), 2 sweeps
    const int gr = tid >> 2;                  // 0..63
    const int gk = (tid & 3) << 2;            // 0,4,8,12

    const float* Xg = X  + (size_t)(bm + gr) * D_DIM + gk;
    const float* Wg = Wm + (size_t)(bn + gr) * D_DIM + gk;

    // acc[i][j]: rows i=0..7; j = q*2+h -> cols bn0 + q*32 + h*2 + {0,1}
    u64t acc[8][4];
#pragma unroll
    for (int i = 0; i < 8; i++)
#pragma unroll
        for (int j = 0; j < 4; j++) acc[i][j] = 0ull;

    // prologue: chunk 0 -> buffer 0
    {
        float4 a0 = *(const float4*)(Xg);
        float4 a1 = *(const float4*)(Xg + (size_t)64 * D_DIM);
        float4 b0 = *(const float4*)(Wg);
        float4 b1 = *(const float4*)(Wg + (size_t)64 * D_DIM);
#pragma unroll
        for (int c = 0; c < 4; c++) {
            As[0][gk + c][gr]      = ((const float*)&a0)[c];
            As[0][gk + c][gr + 64] = ((const float*)&a1)[c];
            Bs[0][gk + c][gr]      = ((const float*)&b0)[c];
            Bs[0][gk + c][gr + 64] = ((const float*)&b1)[c];
        }
    }
    __syncthreads();

    for (int kt = 1; kt <= NKT; kt++) {
        const int buf = (kt - 1) & 1;

        float4 na0, na1, nb0, nb1;
        if (kt < NKT) {
            const int k0 = kt * BKT;
            na0 = *(const float4*)(Xg + k0);
            na1 = *(const float4*)(Xg + k0 + (size_t)64 * D_DIM);
            nb0 = *(const float4*)(Wg + k0);
            nb1 = *(const float4*)(Wg + k0 + (size_t)64 * D_DIM);
        }

#pragma unroll
        for (int k = 0; k < BKT; k++) {
            float4 a0 = *(const float4*)&As[buf][k][tm0];
            float4 a1 = *(const float4*)&As[buf][k][tm0 + 4];
            u64t ad[8];
            ad[0] = pack_dup(a0.x); ad[1] = pack_dup(a0.y);
            ad[2] = pack_dup(a0.z); ad[3] = pack_dup(a0.w);
            ad[4] = pack_dup(a1.x); ad[5] = pack_dup(a1.y);
            ad[6] = pack_dup(a1.z); ad[7] = pack_dup(a1.w);

            u64t bp[4];
#pragma unroll
            for (int q = 0; q < 2; q++) {
                // 8 lanes (ln) cover one contiguous 128B block: conflict-free
                ulonglong2 b2 = *(const ulonglong2*)&Bs[buf][k][bn0 + q * 32];
                bp[q * 2 + 0] = b2.x;
                bp[q * 2 + 1] = b2.y;
            }

#pragma unroll
            for (int i = 0; i < 8; i++)
#pragma unroll
                for (int j = 0; j < 4; j++)
                    ffma2(acc[i][j], ad[i], bp[j]);
        }

        if (kt < NKT) {
            const int nbuf = kt & 1;
#pragma unroll
            for (int c = 0; c < 4; c++) {
                As[nbuf][gk + c][gr]      = ((const float*)&na0)[c];
                As[nbuf][gk + c][gr + 64] = ((const float*)&na1)[c];
                Bs[nbuf][gk + c][gr]      = ((const float*)&nb0)[c];
                Bs[nbuf][gk + c][gr + 64] = ((const float*)&nb1)[c];
            }
        }
        __syncthreads();
    }

    // epilogue: + bias (scalar fp32 adds, bit-identical), store Y
#pragma unroll
    for (int q = 0; q < 2; q++) {
        const int col = bn + bn0 + q * 32;
        const float4 bi = *(const float4*)(bias + col);
#pragma unroll
        for (int i = 0; i < 8; i++) {
            float v0, v1, v2, v3;
            unpack2(acc[i][q * 2 + 0], v0, v1);
            unpack2(acc[i][q * 2 + 1], v2, v3);
            float4 o = {v0 + bi.x, v1 + bi.y, v2 + bi.z, v3 + bi.w};
            *(float4*)(g_Y + (size_t)(bm + tm0 + i) * D_DIM + col) = o;
        }
    }
}

// ---------------------------------------------------------------------------
// Fused fwd+bwd LIF scan, time-chunked with warm-up.
// v' = v + (c-v)*0.5 contracts EXACTLY by 0.5/step, so after ~30 warm-up
// steps the state is bit-identical to the true one; W_UP=64 gives 2x slack
// (was 96 — trimmed for ~9% less read traffic). 128-thread blocks double the
// CTA count for better wave balance on this DRAM-bound kernel.
// ---------------------------------------------------------------------------
#define L_CH  256
#define W_UP  64
#define NCH   (T_DIM / L_CH)
#define UNR   16

__device__ __forceinline__ void lif_step(float& v, float c, bool& s) {
    v = v + (c - v) * 0.5f;
    s = (v >= 1.0f);
    v = s ? 0.0f : v;
}

__global__ void scan_kernel(float* __restrict__ out) {
    const int l  = blockIdx.x * blockDim.x + threadIdx.x;
    const int t0 = blockIdx.y * L_CH;
    unsigned fb[L_CH / 32];

    float v = 0.0f;
    {
        const int tb = (t0 - W_UP < 0) ? 0 : (t0 - W_UP);
        for (int tw = tb; tw < t0; tw += UNR) {
            float c[UNR];
#pragma unroll
            for (int i = 0; i < UNR; i++) c[i] = g_Y[(size_t)(tw + i) * BD + l];
#pragma unroll
            for (int i = 0; i < UNR; i++) { bool s; lif_step(v, c[i], s); }
        }
#pragma unroll
        for (int w = 0; w < L_CH / 32; w++) {
            unsigned bits = 0;
#pragma unroll 1
            for (int h = 0; h < 2; h++) {
                float c[UNR];
#pragma unroll
                for (int i = 0; i < UNR; i++)
                    c[i] = g_Y[(size_t)(t0 + w * 32 + h * UNR + i) * BD + l];
#pragma unroll
                for (int i = 0; i < UNR; i++) {
                    bool s; lif_step(v, c[i], s);
                    bits |= (unsigned)s << (h * UNR + i);
                }
            }
            fb[w] = bits;
        }
    }

    v = 0.0f;
    {
        const int te = (t0 + L_CH + W_UP > T_DIM) ? T_DIM : (t0 + L_CH + W_UP);
        for (int tw = te; tw > t0 + L_CH; tw -= UNR) {
            float c[UNR];
#pragma unroll
            for (int i = 0; i < UNR; i++) c[i] = g_Y[(size_t)(tw - 1 - i) * BD + l];
#pragma unroll
            for (int i = 0; i < UNR; i++) { bool s; lif_step(v, c[i], s); }
        }
#pragma unroll
        for (int w = L_CH / 32 - 1; w >= 0; w--) {
            const unsigned bits = fb[w];
#pragma unroll 1
            for (int h = 1; h >= 0; h--) {
                float c[UNR];
#pragma unroll
                for (int i = 0; i < UNR; i++)
                    c[i] = g_Y[(size_t)(t0 + w * 32 + h * UNR + (UNR - 1) - i) * BD + l];
#pragma unroll
                for (int i = 0; i < UNR; i++) {
                    const int ti = h * UNR + (UNR - 1) - i;
                    bool s; lif_step(v, c[i], s);
                    out[(size_t)(t0 + w * 32 + ti) * BD + l] =
                        (s ? 1.0f : 0.0f) + (float)((bits >> ti) & 1u);
                }
            }
        }
    }
}

// ---------------------------------------------------------------------------
extern "C" void kernel_launch(void* const* d_in, const int* in_sizes, int n_in,
                              void* d_out, int out_size) {
    const float* x = (const float*)d_in[0];
    const float* W = (const float*)d_in[1];
    const float* b = (const float*)d_in[2];
    float* out = (float*)d_out;

    dim3 ggrid(D_DIM / BNT, M_DIM / BMT);   // (4, 512): n inner -> X L2 reuse
    sgemm_kernel<<<ggrid, 256>>>(x, W, b);

    dim3 sgrid(BD / 128, NCH);              // (128, 8) = 1024 CTAs
    scan_kernel<<<sgrid, 128>>>(out);
}